// round 1
// baseline (speedup 1.0000x reference)
#include <cuda_runtime.h>

// Problem constants: B=64, N=32, H=100, D=400, A=200
#define BB 64
#define NN 32
#define HH 100
#define DD 400
#define AA 200

// Scratch (allocation-free: __device__ globals)
__device__ float g_pl[BB * HH * AA];   // [b][h][a] : log_vec @ Wl^T + b1
__device__ float g_pn[BB * NN * AA];   // [b][n][a] : news_vec @ Wn^T

// ---------------- helpers ----------------
__device__ __forceinline__ unsigned long long fma2(unsigned long long a,
                                                   unsigned long long b,
                                                   unsigned long long c) {
    unsigned long long d;
    asm("fma.rn.f32x2 %0, %1, %2, %3;" : "=l"(d) : "l"(a), "l"(b), "l"(c));
    return d;
}
__device__ __forceinline__ unsigned long long pack2(float x, float y) {
    unsigned long long d;
    asm("mov.b64 %0, {%1, %2};" : "=l"(d) : "f"(x), "f"(y));
    return d;
}
__device__ __forceinline__ float tanh_fast(float x) {
    float y;
    asm("tanh.approx.f32 %0, %1;" : "=f"(y) : "f"(x));
    return y;
}

// ---------------- Phase 1: GEMM ----------------
// out[m][a] = sum_k X[m*400+k] * W1[a*800 + koff + k]  (+ bias[a] if use_bias)
// which_out: 0 -> g_pn, 1 -> g_pl
// BM=64, BN=64, BK=16; 256 threads; 4x4 register tile per thread, f32x2 packed FMA.
__global__ __launch_bounds__(256) void gemm_kernel(
    const float* __restrict__ X, const float* __restrict__ W1, int koff,
    const float* __restrict__ bias, int which_out)
{
    const int BK = 16, PAD = 4;
    __shared__ float Xs[BK][64 + PAD];
    __shared__ float Ws[BK][64 + PAD];

    float* out = which_out ? g_pl : g_pn;

    int tid = threadIdx.x;
    int tx = tid & 15;        // a-dim thread coord (0..15)
    int ty = tid >> 4;        // m-dim thread coord (0..15)
    int bm = blockIdx.y * 64;
    int bn = blockIdx.x * 64;

    int l_r = tid >> 2;           // 0..63 : row within tile (m or a)
    int l_k = (tid & 3) << 2;     // 0,4,8,12 : k start (float4)

    unsigned long long acc[4][2];
#pragma unroll
    for (int i = 0; i < 4; i++) { acc[i][0] = 0ULL; acc[i][1] = 0ULL; }

    for (int k0 = 0; k0 < DD; k0 += BK) {
        // stage loads to registers
        float4 xv = *reinterpret_cast<const float4*>(X + (bm + l_r) * DD + k0 + l_k);
        int arow = bn + l_r;
        float4 wv = make_float4(0.f, 0.f, 0.f, 0.f);
        if (arow < AA)
            wv = *reinterpret_cast<const float4*>(W1 + arow * (2 * DD) + koff + k0 + l_k);

        __syncthreads();   // protect smem from previous iteration's readers
        Xs[l_k + 0][l_r] = xv.x;
        Xs[l_k + 1][l_r] = xv.y;
        Xs[l_k + 2][l_r] = xv.z;
        Xs[l_k + 3][l_r] = xv.w;
        Ws[l_k + 0][l_r] = wv.x;
        Ws[l_k + 1][l_r] = wv.y;
        Ws[l_k + 2][l_r] = wv.z;
        Ws[l_k + 3][l_r] = wv.w;
        __syncthreads();

#pragma unroll
        for (int k = 0; k < BK; k++) {
            float4 xq = *reinterpret_cast<float4*>(&Xs[k][ty * 4]);
            ulonglong2 wq = *reinterpret_cast<ulonglong2*>(&Ws[k][tx * 4]);
            unsigned long long x0 = pack2(xq.x, xq.x);
            unsigned long long x1 = pack2(xq.y, xq.y);
            unsigned long long x2 = pack2(xq.z, xq.z);
            unsigned long long x3 = pack2(xq.w, xq.w);
            acc[0][0] = fma2(x0, wq.x, acc[0][0]);
            acc[0][1] = fma2(x0, wq.y, acc[0][1]);
            acc[1][0] = fma2(x1, wq.x, acc[1][0]);
            acc[1][1] = fma2(x1, wq.y, acc[1][1]);
            acc[2][0] = fma2(x2, wq.x, acc[2][0]);
            acc[2][1] = fma2(x2, wq.y, acc[2][1]);
            acc[3][0] = fma2(x3, wq.x, acc[3][0]);
            acc[3][1] = fma2(x3, wq.y, acc[3][1]);
        }
    }

#pragma unroll
    for (int i = 0; i < 4; i++) {
        int m = bm + ty * 4 + i;
#pragma unroll
        for (int jc = 0; jc < 2; jc++) {
            float2 v = *reinterpret_cast<float2*>(&acc[i][jc]);
            int a0 = bn + tx * 4 + jc * 2;
            if (a0 < AA) {  // a0 even, AA even -> a0+1 < AA too
                float bx = bias ? bias[a0] : 0.f;
                float by = bias ? bias[a0 + 1] : 0.f;
                out[m * AA + a0] = v.x + bx;
                out[m * AA + a0 + 1] = v.y + by;
            }
        }
    }
}

// ---------------- Phase 2: fused tanh-attention ----------------
// One block per (b, group of 4 n). 256 threads = 8 warps.
// logits[n][h] = sum_a tanh(pn[n][a] + pl[h][a]) * W2[a] + b2, masked; softmax over h;
// out[n][d] = sum_h attn[n][h] * log_vec[b][h][d]
__global__ __launch_bounds__(256) void attn_kernel(
    const float* __restrict__ log_vec, const int* __restrict__ log_mask,
    const float* __restrict__ W2, const float* __restrict__ b2,
    float* __restrict__ out)
{
    __shared__ float pn_s[4][AA];      // 3.2 KB
    __shared__ float w2_s[AA];         // 0.8 KB
    __shared__ float at_s[HH][5];      // logits -> attn; pad 5 kills bank conflicts

    int b = blockIdx.y;
    int ng = blockIdx.x;               // 0..7 (group of 4 n)
    int tid = threadIdx.x;
    int lane = tid & 31, warp = tid >> 5;

    // stage pn (4 rows) and W2
    for (int i = tid; i < 4 * AA; i += 256)
        pn_s[i / AA][i % AA] = g_pn[(b * NN + ng * 4) * AA + i];
    for (int i = tid; i < AA; i += 256)
        w2_s[i] = W2[i];
    __syncthreads();

    float b2v = b2[0];

    // logits: warp per h (strided), lanes split over a; pl loaded once, reused x4
    for (int h = warp; h < HH; h += 8) {
        const float* pl = g_pl + (b * HH + h) * AA;
        float a0 = 0.f, a1 = 0.f, a2 = 0.f, a3 = 0.f;
        for (int a = lane; a < AA; a += 32) {
            float p = pl[a];
            float w = w2_s[a];
            a0 = fmaf(tanh_fast(p + pn_s[0][a]), w, a0);
            a1 = fmaf(tanh_fast(p + pn_s[1][a]), w, a1);
            a2 = fmaf(tanh_fast(p + pn_s[2][a]), w, a2);
            a3 = fmaf(tanh_fast(p + pn_s[3][a]), w, a3);
        }
#pragma unroll
        for (int o = 16; o; o >>= 1) {
            a0 += __shfl_xor_sync(0xffffffffu, a0, o);
            a1 += __shfl_xor_sync(0xffffffffu, a1, o);
            a2 += __shfl_xor_sync(0xffffffffu, a2, o);
            a3 += __shfl_xor_sync(0xffffffffu, a3, o);
        }
        if (lane < 4) {
            float v = (lane == 0) ? a0 : (lane == 1) ? a1 : (lane == 2) ? a2 : a3;
            at_s[h][lane] = (log_mask[b * HH + h] == 0) ? -1e9f : (v + b2v);
        }
    }
    __syncthreads();

    // softmax over h, warp j handles n-index j
    if (warp < 4) {
        int j = warp;
        float m = -3e38f;
        for (int h = lane; h < HH; h += 32) m = fmaxf(m, at_s[h][j]);
#pragma unroll
        for (int o = 16; o; o >>= 1) m = fmaxf(m, __shfl_xor_sync(0xffffffffu, m, o));
        float s = 0.f;
        for (int h = lane; h < HH; h += 32) {
            float e = __expf(at_s[h][j] - m);
            at_s[h][j] = e;
            s += e;
        }
#pragma unroll
        for (int o = 16; o; o >>= 1) s += __shfl_xor_sync(0xffffffffu, s, o);
        float r = 1.f / s;
        for (int h = lane; h < HH; h += 32) at_s[h][j] *= r;
    }
    __syncthreads();

    // output: thread per d; log_vec value reused across the 4 n
    const float* lv_base = log_vec + b * HH * DD;
    int nbase = b * NN + ng * 4;
    for (int d = tid; d < DD; d += 256) {
        float o0 = 0.f, o1 = 0.f, o2 = 0.f, o3 = 0.f;
#pragma unroll 4
        for (int h = 0; h < HH; h++) {
            float v = lv_base[h * DD + d];
            o0 = fmaf(at_s[h][0], v, o0);
            o1 = fmaf(at_s[h][1], v, o1);
            o2 = fmaf(at_s[h][2], v, o2);
            o3 = fmaf(at_s[h][3], v, o3);
        }
        out[(nbase + 0) * DD + d] = o0;
        out[(nbase + 1) * DD + d] = o1;
        out[(nbase + 2) * DD + d] = o2;
        out[(nbase + 3) * DD + d] = o3;
    }
}

// ---------------- launch ----------------
extern "C" void kernel_launch(void* const* d_in, const int* in_sizes, int n_in,
                              void* d_out, int out_size) {
    const float* log_vec  = (const float*)d_in[0];   // [64,100,400] f32
    const int*   log_mask = (const int*)d_in[1];     // [64,100] i32
    const float* news_vec = (const float*)d_in[2];   // [64,32,400] f32
    const float* W1       = (const float*)d_in[3];   // [200,800] f32
    const float* b1       = (const float*)d_in[4];   // [200] f32
    const float* W2       = (const float*)d_in[5];   // [1,200] f32
    const float* b2       = (const float*)d_in[6];   // [1] f32
    float* out = (float*)d_out;                      // [64,32,400] f32

    // pl = log_vec @ Wl^T + b1  (Wl = W1[:,400:800]) : M=6400
    gemm_kernel<<<dim3(4, 100), 256>>>(log_vec, W1, DD, b1, /*which_out=*/1);
    // pn = news_vec @ Wn^T      (Wn = W1[:,0:400])   : M=2048
    gemm_kernel<<<dim3(4, 32), 256>>>(news_vec, W1, 0, nullptr, /*which_out=*/0);
    // fused tanh + softmax + attention
    attn_kernel<<<dim3(NN / 4, BB), 256>>>(log_vec, log_mask, W2, b2, out);
}

// round 2
// speedup vs baseline: 1.1271x; 1.1271x over previous
#include <cuda_runtime.h>

// Problem constants: B=64, N=32, H=100, D=400, A=200
#define BB 64
#define NN 32
#define HH 100
#define DD 400
#define AA 200

// Scratch (allocation-free: __device__ globals)
__device__ float g_pl[BB * HH * AA];   // [b][h][a] : log_vec @ Wl^T + b1
__device__ float g_pn[BB * NN * AA];   // [b][n][a] : news_vec @ Wn^T

typedef unsigned long long ull;

// ---------------- helpers ----------------
__device__ __forceinline__ ull fma2(ull a, ull b, ull c) {
    ull d;
    asm("fma.rn.f32x2 %0, %1, %2, %3;" : "=l"(d) : "l"(a), "l"(b), "l"(c));
    return d;
}
__device__ __forceinline__ float tanh_fast(float x) {
    float y;
    asm("tanh.approx.f32 %0, %1;" : "=f"(y) : "f"(x));
    return y;
}

// ---------------- Phase 1: fused GEMM (pl + pn in one launch) ----------------
// by < 100 : pl rows (log_vec, Wl = W1[:,400:800], +b1)
// by >= 100: pn rows (news_vec, Wn = W1[:,0:400])
// BM=64, BN=64, BK=16, 128 threads, 8m x 4a per-thread tile, f32x2 FMA.
// Xs2 stores each x duplicated (x,x) so packed broadcasts come straight from LDS.
__global__ __launch_bounds__(128) void gemm_kernel(
    const float* __restrict__ log_vec, const float* __restrict__ news_vec,
    const float* __restrict__ W1, const float* __restrict__ b1)
{
    const int BK = 16;
    __shared__ float Xs2[BK][132];   // [k][2*r] duplicated pairs (128 used + pad)
    __shared__ float Ws[BK][68];     // [k][a]

    int by = blockIdx.y;
    const float* X;
    float* out;
    int koff, bm;
    bool add_bias;
    if (by < 100) { X = log_vec;  out = g_pl; koff = DD; bm = by * 64;         add_bias = true;  }
    else          { X = news_vec; out = g_pn; koff = 0;  bm = (by - 100) * 64; add_bias = false; }
    int bn = blockIdx.x * 64;

    int tid = threadIdx.x;
    int tx = tid & 15;      // a-group (4 cols)
    int ty = tid >> 4;      // m-group (8 rows)

    float4 xr[2], wr[2];

    // stage global->regs for k-block starting at k0
    auto ldg_tiles = [&](int k0) {
#pragma unroll
        for (int u = 0; u < 2; u++) {
            int idx = tid + u * 128;         // 0..255
            int r = idx >> 2;                // 0..63
            int kk = (idx & 3) << 2;         // 0,4,8,12
            xr[u] = *reinterpret_cast<const float4*>(X + (bm + r) * DD + k0 + kk);
            int arow = bn + r;
            wr[u] = (arow < AA)
                ? *reinterpret_cast<const float4*>(W1 + arow * (2 * DD) + koff + k0 + kk)
                : make_float4(0.f, 0.f, 0.f, 0.f);
        }
    };
    auto sts_tiles = [&]() {
#pragma unroll
        for (int u = 0; u < 2; u++) {
            int idx = tid + u * 128;
            int r = idx >> 2;
            int kk = (idx & 3) << 2;
            float xv[4] = {xr[u].x, xr[u].y, xr[u].z, xr[u].w};
            float wv[4] = {wr[u].x, wr[u].y, wr[u].z, wr[u].w};
#pragma unroll
            for (int j = 0; j < 4; j++) {
                // duplicated pair store (float2 aligned: 2r even)
                *reinterpret_cast<float2*>(&Xs2[kk + j][2 * r]) = make_float2(xv[j], xv[j]);
                Ws[kk + j][r] = wv[j];
            }
        }
    };

    ull acc[8][2];
#pragma unroll
    for (int i = 0; i < 8; i++) { acc[i][0] = 0ULL; acc[i][1] = 0ULL; }

    ldg_tiles(0);
    for (int kb = 0; kb < DD / BK; kb++) {
        __syncthreads();      // protect smem from previous iteration's readers
        sts_tiles();
        __syncthreads();
        if (kb + 1 < DD / BK) ldg_tiles((kb + 1) * BK);   // hide LDG under FMA below

#pragma unroll
        for (int k = 0; k < BK; k++) {
            // 8 duplicated x pairs: (x0,x0,x1,x1,...) -> 8 ull broadcasts
            float4 xd0 = *reinterpret_cast<float4*>(&Xs2[k][ty * 16 + 0]);
            float4 xd1 = *reinterpret_cast<float4*>(&Xs2[k][ty * 16 + 4]);
            float4 xd2 = *reinterpret_cast<float4*>(&Xs2[k][ty * 16 + 8]);
            float4 xd3 = *reinterpret_cast<float4*>(&Xs2[k][ty * 16 + 12]);
            ulonglong2 wq = *reinterpret_cast<ulonglong2*>(&Ws[k][tx * 4]);
            ull xp[8];
            xp[0] = reinterpret_cast<ull*>(&xd0)[0];
            xp[1] = reinterpret_cast<ull*>(&xd0)[1];
            xp[2] = reinterpret_cast<ull*>(&xd1)[0];
            xp[3] = reinterpret_cast<ull*>(&xd1)[1];
            xp[4] = reinterpret_cast<ull*>(&xd2)[0];
            xp[5] = reinterpret_cast<ull*>(&xd2)[1];
            xp[6] = reinterpret_cast<ull*>(&xd3)[0];
            xp[7] = reinterpret_cast<ull*>(&xd3)[1];
#pragma unroll
            for (int i = 0; i < 8; i++) {
                acc[i][0] = fma2(xp[i], wq.x, acc[i][0]);
                acc[i][1] = fma2(xp[i], wq.y, acc[i][1]);
            }
        }
    }

    // epilogue: coalesced float2 stores over a
#pragma unroll
    for (int i = 0; i < 8; i++) {
        int m = bm + ty * 8 + i;
#pragma unroll
        for (int jc = 0; jc < 2; jc++) {
            int a0 = bn + tx * 4 + jc * 2;
            if (a0 < AA) {   // a0 even, AA even -> a0+1 valid too
                float2 v = *reinterpret_cast<float2*>(&acc[i][jc]);
                if (add_bias) { v.x += b1[a0]; v.y += b1[a0 + 1]; }
                *reinterpret_cast<float2*>(out + m * AA + a0) = v;
            }
        }
    }
}

// ---------------- Phase 2: fused tanh-attention ----------------
// One block per (b, group of 8 n). 256 threads. pl[b] fully staged in smem;
// each thread computes one (n,h) logit dot serially -> zero cross-lane reductions.
#define PLPAD 202   // even (float2-aligned), 202 mod 32 = 10 -> only 2-way LDS conflicts
#define ATPAD 104

__global__ __launch_bounds__(256) void attn_kernel(
    const float* __restrict__ log_vec, const int* __restrict__ log_mask,
    const float* __restrict__ W2, const float* __restrict__ b2,
    float* __restrict__ out)
{
    extern __shared__ float sm[];
    float* pl_s = sm;                       // [100][PLPAD]
    float* pn_s = pl_s + HH * PLPAD;        // [8][200]
    float* w2_s = pn_s + 8 * AA;            // [200]
    float* at_s = w2_s + AA;                // [8][ATPAD] logits -> attn

    int b = blockIdx.y;
    int ng = blockIdx.x;                    // 0..3 (group of 8 n)
    int tid = threadIdx.x;
    int lane = tid & 31, warp = tid >> 5;

    // stage pl[b] (100x200), pn (8x200), W2
    const float4* plg = reinterpret_cast<const float4*>(g_pl + b * HH * AA);
    for (int i = tid; i < HH * AA / 4; i += 256) {     // 5000 float4
        int row = i / (AA / 4);
        int c4 = (i % (AA / 4)) * 4;
        float4 v = plg[i];
        float* dst = pl_s + row * PLPAD + c4;
        dst[0] = v.x; dst[1] = v.y; dst[2] = v.z; dst[3] = v.w;
    }
    const float4* png = reinterpret_cast<const float4*>(g_pn + (b * NN + ng * 8) * AA);
    for (int i = tid; i < 8 * AA / 4; i += 256)
        reinterpret_cast<float4*>(pn_s)[i] = png[i];
    for (int i = tid; i < AA; i += 256)
        w2_s[i] = W2[i];
    __syncthreads();

    float b2v = b2[0];

    // logits: thread -> (n,h) pair; serial dot over a (2 accumulators for ILP)
    for (int p = tid; p < 8 * HH; p += 256) {
        int n = p / HH, h = p % HH;
        const float* plr = pl_s + h * PLPAD;
        const float* pnr = pn_s + n * AA;
        float s0 = 0.f, s1 = 0.f;
#pragma unroll 4
        for (int a = 0; a < AA; a += 2) {
            float2 pv = *reinterpret_cast<const float2*>(plr + a);
            float2 nv = *reinterpret_cast<const float2*>(pnr + a);
            float2 wv = *reinterpret_cast<const float2*>(w2_s + a);
            s0 = fmaf(tanh_fast(pv.x + nv.x), wv.x, s0);
            s1 = fmaf(tanh_fast(pv.y + nv.y), wv.y, s1);
        }
        float s = s0 + s1;
        at_s[n * ATPAD + h] = (log_mask[b * HH + h] == 0) ? -1e9f : (s + b2v);
    }
    __syncthreads();

    // softmax over h: warp j handles n-index j
    {
        float* row = at_s + warp * ATPAD;
        float m = -3e38f;
        for (int h = lane; h < HH; h += 32) m = fmaxf(m, row[h]);
#pragma unroll
        for (int o = 16; o; o >>= 1) m = fmaxf(m, __shfl_xor_sync(0xffffffffu, m, o));
        float s = 0.f;
        for (int h = lane; h < HH; h += 32) {
            float e = __expf(row[h] - m);
            row[h] = e;
            s += e;
        }
#pragma unroll
        for (int o = 16; o; o >>= 1) s += __shfl_xor_sync(0xffffffffu, s, o);
        float r = 1.f / s;
        for (int h = lane; h < HH; h += 32) row[h] *= r;
    }
    __syncthreads();

    // output: thread per d; log_vec value reused across 8 n (broadcast attn LDS)
    const float* lv = log_vec + b * HH * DD;
    int nbase = b * NN + ng * 8;
    for (int d = tid; d < DD; d += 256) {
        float acc[8];
#pragma unroll
        for (int n = 0; n < 8; n++) acc[n] = 0.f;
#pragma unroll 2
        for (int h = 0; h < HH; h++) {
            float v = lv[h * DD + d];
#pragma unroll
            for (int n = 0; n < 8; n++)
                acc[n] = fmaf(at_s[n * ATPAD + h], v, acc[n]);
        }
#pragma unroll
        for (int n = 0; n < 8; n++)
            out[(nbase + n) * DD + d] = acc[n];
    }
}

// ---------------- launch ----------------
extern "C" void kernel_launch(void* const* d_in, const int* in_sizes, int n_in,
                              void* d_out, int out_size) {
    const float* log_vec  = (const float*)d_in[0];   // [64,100,400] f32
    const int*   log_mask = (const int*)d_in[1];     // [64,100] i32
    const float* news_vec = (const float*)d_in[2];   // [64,32,400] f32
    const float* W1       = (const float*)d_in[3];   // [200,800] f32
    const float* b1       = (const float*)d_in[4];   // [200] f32
    const float* W2       = (const float*)d_in[5];   // [1,200] f32
    const float* b2       = (const float*)d_in[6];   // [1] f32
    float* out = (float*)d_out;                      // [64,32,400] f32

    // fused pl+pn GEMM: 100 pl row-blocks + 32 pn row-blocks, 4 col-blocks
    gemm_kernel<<<dim3(4, 132), 128>>>(log_vec, news_vec, W1, b1);

    // fused tanh + softmax + attention (91.3 KB dynamic smem)
    const int smem_bytes = (HH * PLPAD + 8 * AA + AA + 8 * ATPAD) * 4;
    cudaFuncSetAttribute(attn_kernel, cudaFuncAttributeMaxDynamicSharedMemorySize, smem_bytes);
    attn_kernel<<<dim3(NN / 8, BB), 256, smem_bytes>>>(log_vec, log_mask, W2, b2, out);
}

// round 3
// speedup vs baseline: 1.1688x; 1.0369x over previous
#include <cuda_runtime.h>

// Problem constants: B=64, N=32, H=100, D=400, A=200
#define BB 64
#define NN 32
#define HH 100
#define DD 400
#define AA 200

// Scratch (allocation-free: __device__ globals)
__device__ float g_pl[BB * HH * AA];   // [b][h][a] : log_vec @ Wl^T + b1
__device__ float g_pn[BB * NN * AA];   // [b][n][a] : news_vec @ Wn^T

typedef unsigned long long ull;

// ---------------- helpers ----------------
__device__ __forceinline__ ull fma2(ull a, ull b, ull c) {
    ull d;
    asm("fma.rn.f32x2 %0, %1, %2, %3;" : "=l"(d) : "l"(a), "l"(b), "l"(c));
    return d;
}
__device__ __forceinline__ float tanh_fast(float x) {
    float y;
    asm("tanh.approx.f32 %0, %1;" : "=f"(y) : "f"(x));
    return y;
}

// ---------------- Phase 1: fused GEMM (pl + pn in one launch) ----------------
// by < 100 : pl rows (log_vec, Wl = W1[:,400:800], +b1)
// by >= 100: pn rows (news_vec, Wn = W1[:,0:400])
// BM=64, BN=64, BK=16, 128 threads, 8m x 4a per-thread tile, f32x2 FMA.
__global__ __launch_bounds__(128) void gemm_kernel(
    const float* __restrict__ log_vec, const float* __restrict__ news_vec,
    const float* __restrict__ W1, const float* __restrict__ b1)
{
    const int BK = 16;
    __shared__ float Xs2[BK][132];   // [k][2*r] duplicated pairs
    __shared__ float Ws[BK][68];     // [k][a]

    int by = blockIdx.y;
    const float* X;
    float* out;
    int koff, bm;
    bool add_bias;
    if (by < 100) { X = log_vec;  out = g_pl; koff = DD; bm = by * 64;         add_bias = true;  }
    else          { X = news_vec; out = g_pn; koff = 0;  bm = (by - 100) * 64; add_bias = false; }
    int bn = blockIdx.x * 64;

    int tid = threadIdx.x;
    int tx = tid & 15;      // a-group (4 cols)
    int ty = tid >> 4;      // m-group (8 rows)

    float4 xr[2], wr[2];

    auto ldg_tiles = [&](int k0) {
#pragma unroll
        for (int u = 0; u < 2; u++) {
            int idx = tid + u * 128;
            int r = idx >> 2;
            int kk = (idx & 3) << 2;
            xr[u] = *reinterpret_cast<const float4*>(X + (bm + r) * DD + k0 + kk);
            int arow = bn + r;
            wr[u] = (arow < AA)
                ? *reinterpret_cast<const float4*>(W1 + arow * (2 * DD) + koff + k0 + kk)
                : make_float4(0.f, 0.f, 0.f, 0.f);
        }
    };
    auto sts_tiles = [&]() {
#pragma unroll
        for (int u = 0; u < 2; u++) {
            int idx = tid + u * 128;
            int r = idx >> 2;
            int kk = (idx & 3) << 2;
            float xv[4] = {xr[u].x, xr[u].y, xr[u].z, xr[u].w};
            float wv[4] = {wr[u].x, wr[u].y, wr[u].z, wr[u].w};
#pragma unroll
            for (int j = 0; j < 4; j++) {
                *reinterpret_cast<float2*>(&Xs2[kk + j][2 * r]) = make_float2(xv[j], xv[j]);
                Ws[kk + j][r] = wv[j];
            }
        }
    };

    ull acc[8][2];
#pragma unroll
    for (int i = 0; i < 8; i++) { acc[i][0] = 0ULL; acc[i][1] = 0ULL; }

    ldg_tiles(0);
    for (int kb = 0; kb < DD / BK; kb++) {
        __syncthreads();
        sts_tiles();
        __syncthreads();
        if (kb + 1 < DD / BK) ldg_tiles((kb + 1) * BK);

#pragma unroll
        for (int k = 0; k < BK; k++) {
            float4 xd0 = *reinterpret_cast<float4*>(&Xs2[k][ty * 16 + 0]);
            float4 xd1 = *reinterpret_cast<float4*>(&Xs2[k][ty * 16 + 4]);
            float4 xd2 = *reinterpret_cast<float4*>(&Xs2[k][ty * 16 + 8]);
            float4 xd3 = *reinterpret_cast<float4*>(&Xs2[k][ty * 16 + 12]);
            ulonglong2 wq = *reinterpret_cast<ulonglong2*>(&Ws[k][tx * 4]);
            ull xp[8];
            xp[0] = reinterpret_cast<ull*>(&xd0)[0];
            xp[1] = reinterpret_cast<ull*>(&xd0)[1];
            xp[2] = reinterpret_cast<ull*>(&xd1)[0];
            xp[3] = reinterpret_cast<ull*>(&xd1)[1];
            xp[4] = reinterpret_cast<ull*>(&xd2)[0];
            xp[5] = reinterpret_cast<ull*>(&xd2)[1];
            xp[6] = reinterpret_cast<ull*>(&xd3)[0];
            xp[7] = reinterpret_cast<ull*>(&xd3)[1];
#pragma unroll
            for (int i = 0; i < 8; i++) {
                acc[i][0] = fma2(xp[i], wq.x, acc[i][0]);
                acc[i][1] = fma2(xp[i], wq.y, acc[i][1]);
            }
        }
    }

#pragma unroll
    for (int i = 0; i < 8; i++) {
        int m = bm + ty * 8 + i;
#pragma unroll
        for (int jc = 0; jc < 2; jc++) {
            int a0 = bn + tx * 4 + jc * 2;
            if (a0 < AA) {
                float2 v = *reinterpret_cast<float2*>(&acc[i][jc]);
                if (add_bias) { v.x += b1[a0]; v.y += b1[a0 + 1]; }
                *reinterpret_cast<float2*>(out + m * AA + a0) = v;
            }
        }
    }
}

// ---------------- Phase 2: fused tanh-attention (occupancy-first) ----------------
// Block = (b, group of 4 n), 128 threads, grid 512.
// Logits: thread = h (0..99), 4 n-accumulators -> 4 independent tanh chains/iter.
// pl staged in 40-wide a-chunks (coalesced load, conflict-free stride-41 reads).
#define CS 40          // a-chunk width (200 = 5 * 40)
#define CPAD 41        // row stride: gcd(41,32)=1 -> conflict-free thread-per-h reads
#define ATP 112        // at_s row stride

__global__ __launch_bounds__(128) void attn_kernel(
    const float* __restrict__ log_vec, const int* __restrict__ log_mask,
    const float* __restrict__ W2, const float* __restrict__ b2,
    float* __restrict__ out)
{
    __shared__ float pl_s[HH][CPAD];   // 16.4 KB
    __shared__ float pn_s[4][AA];      // 3.2 KB
    __shared__ float w2_s[AA];         // 0.8 KB
    __shared__ float at_s[4][ATP];     // 1.8 KB

    int b = blockIdx.y;
    int ng = blockIdx.x;               // 0..7
    int tid = threadIdx.x;
    int lane = tid & 31, warp = tid >> 5;

    // stage pn (4 rows) and W2 (contiguous float4 loads)
    const float4* png = reinterpret_cast<const float4*>(g_pn + (b * NN + ng * 4) * AA);
    for (int i = tid; i < 4 * AA / 4; i += 128)
        reinterpret_cast<float4*>(&pn_s[0][0])[i] = png[i];
    for (int i = tid; i < AA / 4; i += 128)
        reinterpret_cast<float4*>(w2_s)[i] = reinterpret_cast<const float4*>(W2)[i];

    float l0 = 0.f, l1 = 0.f, l2 = 0.f, l3 = 0.f;
    const int hh = tid;                // thread's h (valid if < 100)
    const float* plg = g_pl + b * HH * AA;

    for (int a0 = 0; a0 < AA; a0 += CS) {
        __syncthreads();               // protect pl_s from previous chunk's readers
        // cooperative coalesced load of pl[:, a0:a0+40]  (100 rows x 10 float4)
        for (int i = tid; i < HH * (CS / 4); i += 128) {
            int row = i / (CS / 4);
            int c = (i % (CS / 4)) * 4;
            float4 v = *reinterpret_cast<const float4*>(plg + row * AA + a0 + c);
            float* dst = &pl_s[row][c];
            dst[0] = v.x; dst[1] = v.y; dst[2] = v.z; dst[3] = v.w;
        }
        __syncthreads();

        if (hh < HH) {
#pragma unroll
            for (int aa = 0; aa < CS; aa++) {
                int a = a0 + aa;
                float p = pl_s[hh][aa];     // conflict-free (stride 41)
                float w = w2_s[a];          // broadcast
                l0 = fmaf(tanh_fast(p + pn_s[0][a]), w, l0);
                l1 = fmaf(tanh_fast(p + pn_s[1][a]), w, l1);
                l2 = fmaf(tanh_fast(p + pn_s[2][a]), w, l2);
                l3 = fmaf(tanh_fast(p + pn_s[3][a]), w, l3);
            }
        }
    }

    if (hh < HH) {
        float b2v = b2[0];
        bool masked = (log_mask[b * HH + hh] == 0);
        at_s[0][hh] = masked ? -1e9f : (l0 + b2v);
        at_s[1][hh] = masked ? -1e9f : (l1 + b2v);
        at_s[2][hh] = masked ? -1e9f : (l2 + b2v);
        at_s[3][hh] = masked ? -1e9f : (l3 + b2v);
    }
    __syncthreads();

    // softmax over h: warp j handles n-index j
    {
        float* row = at_s[warp];
        float m = -3e38f;
        for (int h = lane; h < HH; h += 32) m = fmaxf(m, row[h]);
#pragma unroll
        for (int o = 16; o; o >>= 1) m = fmaxf(m, __shfl_xor_sync(0xffffffffu, m, o));
        float s = 0.f;
        for (int h = lane; h < HH; h += 32) {
            float e = __expf(row[h] - m);
            row[h] = e;
            s += e;
        }
#pragma unroll
        for (int o = 16; o; o >>= 1) s += __shfl_xor_sync(0xffffffffu, s, o);
        float r = 1.f / s;
        for (int h = lane; h < HH; h += 32) row[h] *= r;
    }
    __syncthreads();

    // output: thread per d; log_vec value reused across the 4 n
    const float* lv = log_vec + b * HH * DD;
    int nbase = b * NN + ng * 4;
    for (int d = tid; d < DD; d += 128) {
        float o0 = 0.f, o1 = 0.f, o2 = 0.f, o3 = 0.f;
        const float* lvd = lv + d;
#pragma unroll 4
        for (int h = 0; h < HH; h++) {
            float v = lvd[h * DD];
            o0 = fmaf(at_s[0][h], v, o0);
            o1 = fmaf(at_s[1][h], v, o1);
            o2 = fmaf(at_s[2][h], v, o2);
            o3 = fmaf(at_s[3][h], v, o3);
        }
        out[(nbase + 0) * DD + d] = o0;
        out[(nbase + 1) * DD + d] = o1;
        out[(nbase + 2) * DD + d] = o2;
        out[(nbase + 3) * DD + d] = o3;
    }
}

// ---------------- launch ----------------
extern "C" void kernel_launch(void* const* d_in, const int* in_sizes, int n_in,
                              void* d_out, int out_size) {
    const float* log_vec  = (const float*)d_in[0];   // [64,100,400] f32
    const int*   log_mask = (const int*)d_in[1];     // [64,100] i32
    const float* news_vec = (const float*)d_in[2];   // [64,32,400] f32
    const float* W1       = (const float*)d_in[3];   // [200,800] f32
    const float* b1       = (const float*)d_in[4];   // [200] f32
    const float* W2       = (const float*)d_in[5];   // [1,200] f32
    const float* b2       = (const float*)d_in[6];   // [1] f32
    float* out = (float*)d_out;                      // [64,32,400] f32

    // fused pl+pn GEMM: 100 pl row-blocks + 32 pn row-blocks, 4 col-blocks
    gemm_kernel<<<dim3(4, 132), 128>>>(log_vec, news_vec, W1, b1);

    // fused tanh + softmax + attention: 512 blocks, ~22 KB smem -> high occupancy
    attn_kernel<<<dim3(NN / 4, BB), 128>>>(log_vec, log_mask, W2, b2, out);
}

// round 5
// speedup vs baseline: 1.1987x; 1.0256x over previous
#include <cuda_runtime.h>

// Problem constants: B=64, N=32, H=100, D=400, A=200
#define BB 64
#define NN 32
#define HH 100
#define DD 400
#define AA 200

// Scratch (allocation-free: __device__ globals)
__device__ float g_pl[BB * HH * AA];   // [b][h][a] : log_vec @ Wl^T + b1
__device__ float g_pn[BB * NN * AA];   // [b][n][a] : news_vec @ Wn^T

typedef unsigned long long ull;

// ---------------- helpers ----------------
__device__ __forceinline__ ull fma2(ull a, ull b, ull c) {
    ull d;
    asm("fma.rn.f32x2 %0, %1, %2, %3;" : "=l"(d) : "l"(a), "l"(b), "l"(c));
    return d;
}
__device__ __forceinline__ float tanh_fast(float x) {
    float y;
    asm("tanh.approx.f32 %0, %1;" : "=f"(y) : "f"(x));
    return y;
}

// ---------------- Phase 1: fused GEMM (pl + pn in one launch) ----------------
// by < 100 : pl rows (log_vec, Wl = W1[:,400:800], +b1)
// by >= 100: pn rows (news_vec, Wn = W1[:,0:400])
// BM=64, BN=64, BK=16, 128 threads, 8m x 4a per-thread tile, f32x2 FMA.
__global__ __launch_bounds__(128) void gemm_kernel(
    const float* __restrict__ log_vec, const float* __restrict__ news_vec,
    const float* __restrict__ W1, const float* __restrict__ b1)
{
    const int BK = 16;
    __shared__ float Xs2[BK][132];   // [k][2*r] duplicated pairs
    __shared__ float Ws[BK][68];     // [k][a]

    int by = blockIdx.y;
    const float* X;
    float* out;
    int koff, bm;
    bool add_bias;
    if (by < 100) { X = log_vec;  out = g_pl; koff = DD; bm = by * 64;         add_bias = true;  }
    else          { X = news_vec; out = g_pn; koff = 0;  bm = (by - 100) * 64; add_bias = false; }
    int bn = blockIdx.x * 64;

    int tid = threadIdx.x;
    int tx = tid & 15;      // a-group (4 cols)
    int ty = tid >> 4;      // m-group (8 rows)

    float4 xr[2], wr[2];

    auto ldg_tiles = [&](int k0) {
#pragma unroll
        for (int u = 0; u < 2; u++) {
            int idx = tid + u * 128;
            int r = idx >> 2;
            int kk = (idx & 3) << 2;
            xr[u] = *reinterpret_cast<const float4*>(X + (bm + r) * DD + k0 + kk);
            int arow = bn + r;
            wr[u] = (arow < AA)
                ? *reinterpret_cast<const float4*>(W1 + arow * (2 * DD) + koff + k0 + kk)
                : make_float4(0.f, 0.f, 0.f, 0.f);
        }
    };
    auto sts_tiles = [&]() {
#pragma unroll
        for (int u = 0; u < 2; u++) {
            int idx = tid + u * 128;
            int r = idx >> 2;
            int kk = (idx & 3) << 2;
            float xv[4] = {xr[u].x, xr[u].y, xr[u].z, xr[u].w};
            float wv[4] = {wr[u].x, wr[u].y, wr[u].z, wr[u].w};
#pragma unroll
            for (int j = 0; j < 4; j++) {
                *reinterpret_cast<float2*>(&Xs2[kk + j][2 * r]) = make_float2(xv[j], xv[j]);
                Ws[kk + j][r] = wv[j];
            }
        }
    };

    ull acc[8][2];
#pragma unroll
    for (int i = 0; i < 8; i++) { acc[i][0] = 0ULL; acc[i][1] = 0ULL; }

    ldg_tiles(0);
    for (int kb = 0; kb < DD / BK; kb++) {
        __syncthreads();
        sts_tiles();
        __syncthreads();
        if (kb + 1 < DD / BK) ldg_tiles((kb + 1) * BK);

#pragma unroll
        for (int k = 0; k < BK; k++) {
            float4 xd0 = *reinterpret_cast<float4*>(&Xs2[k][ty * 16 + 0]);
            float4 xd1 = *reinterpret_cast<float4*>(&Xs2[k][ty * 16 + 4]);
            float4 xd2 = *reinterpret_cast<float4*>(&Xs2[k][ty * 16 + 8]);
            float4 xd3 = *reinterpret_cast<float4*>(&Xs2[k][ty * 16 + 12]);
            ulonglong2 wq = *reinterpret_cast<ulonglong2*>(&Ws[k][tx * 4]);
            ull xp[8];
            xp[0] = reinterpret_cast<ull*>(&xd0)[0];
            xp[1] = reinterpret_cast<ull*>(&xd0)[1];
            xp[2] = reinterpret_cast<ull*>(&xd1)[0];
            xp[3] = reinterpret_cast<ull*>(&xd1)[1];
            xp[4] = reinterpret_cast<ull*>(&xd2)[0];
            xp[5] = reinterpret_cast<ull*>(&xd2)[1];
            xp[6] = reinterpret_cast<ull*>(&xd3)[0];
            xp[7] = reinterpret_cast<ull*>(&xd3)[1];
#pragma unroll
            for (int i = 0; i < 8; i++) {
                acc[i][0] = fma2(xp[i], wq.x, acc[i][0]);
                acc[i][1] = fma2(xp[i], wq.y, acc[i][1]);
            }
        }
    }

#pragma unroll
    for (int i = 0; i < 8; i++) {
        int m = bm + ty * 8 + i;
#pragma unroll
        for (int jc = 0; jc < 2; jc++) {
            int a0 = bn + tx * 4 + jc * 2;
            if (a0 < AA) {
                float2 v = *reinterpret_cast<float2*>(&acc[i][jc]);
                if (add_bias) { v.x += b1[a0]; v.y += b1[a0 + 1]; }
                *reinterpret_cast<float2*>(out + m * AA + a0) = v;
            }
        }
    }
}

// ---------------- Phase 2: fused tanh-attention (TLP-first) ----------------
// Block = (b, group of 4 n), 512 threads, grid 512 -> 8192 warps (occ ~85%).
// Logits: thread t -> (nsub = t>>7, h = t&127); ONE (n,h) chain per thread.
// pl staged in 40-wide a-chunks (coalesced load, stride-41 conflict-free reads).
#define CS 40          // a-chunk width (200 = 5 * 40)
#define CPAD 41        // gcd(41,32)=1 -> conflict-free thread-per-h reads
#define ATP 112        // at_s row stride

__global__ __launch_bounds__(512, 3) void attn_kernel(
    const float* __restrict__ log_vec, const int* __restrict__ log_mask,
    const float* __restrict__ W2, const float* __restrict__ b2,
    float* __restrict__ out)
{
    __shared__ float pl_s[HH][CPAD];   // 16.4 KB
    __shared__ float pn_s[4][AA];      // 3.2 KB
    __shared__ float w2_s[AA];         // 0.8 KB
    __shared__ float at_s[4][ATP];     // 1.8 KB

    int b = blockIdx.y;
    int ng = blockIdx.x;               // 0..7
    int tid = threadIdx.x;
    int lane = tid & 31, warp = tid >> 5;

    // stage pn (4 rows = 200 float4) and W2 (50 float4) in one pass
    const float4* png = reinterpret_cast<const float4*>(g_pn + (b * NN + ng * 4) * AA);
    if (tid < 4 * AA / 4)
        reinterpret_cast<float4*>(&pn_s[0][0])[tid] = png[tid];
    else if (tid < 4 * AA / 4 + AA / 4)
        reinterpret_cast<float4*>(w2_s)[tid - 4 * AA / 4] =
            reinterpret_cast<const float4*>(W2)[tid - 4 * AA / 4];

    const int nsub = tid >> 7;         // 0..3
    const int hh = tid & 127;          // thread's h (valid if < 100)
    const float* pnr = pn_s[nsub];
    float lacc = 0.f;
    const float* plg = g_pl + b * HH * AA;

    for (int a0 = 0; a0 < AA; a0 += CS) {
        __syncthreads();               // protect pl_s from previous chunk's readers
        // cooperative coalesced load of pl[:, a0:a0+40]  (100 rows x 10 float4)
        for (int i = tid; i < HH * (CS / 4); i += 512) {
            int row = i / (CS / 4);
            int c = (i % (CS / 4)) * 4;
            float4 v = *reinterpret_cast<const float4*>(plg + row * AA + a0 + c);
            float* dst = &pl_s[row][c];
            dst[0] = v.x; dst[1] = v.y; dst[2] = v.z; dst[3] = v.w;
        }
        __syncthreads();

        if (hh < HH) {
#pragma unroll
            for (int aa = 0; aa < CS; aa++) {
                int a = a0 + aa;
                float p = pl_s[hh][aa];      // conflict-free (stride 41)
                lacc = fmaf(tanh_fast(p + pnr[a]), w2_s[a], lacc);  // pn,w2 broadcast
            }
        }
    }

    if (hh < HH) {
        bool masked = (log_mask[b * HH + hh] == 0);
        at_s[nsub][hh] = masked ? -1e9f : (lacc + b2[0]);
    }
    __syncthreads();

    // softmax over h: warp j (0..3) handles n-index j
    if (warp < 4) {
        float* row = at_s[warp];
        float m = -3e38f;
        for (int h = lane; h < HH; h += 32) m = fmaxf(m, row[h]);
#pragma unroll
        for (int o = 16; o; o >>= 1) m = fmaxf(m, __shfl_xor_sync(0xffffffffu, m, o));
        float s = 0.f;
        for (int h = lane; h < HH; h += 32) {
            float e = __expf(row[h] - m);
            row[h] = e;
            s += e;
        }
#pragma unroll
        for (int o = 16; o; o >>= 1) s += __shfl_xor_sync(0xffffffffu, s, o);
        float r = 1.f / s;
        for (int h = lane; h < HH; h += 32) row[h] *= r;
    }
    __syncthreads();

    // output: thread per d (400 of 512 active); log_vec value reused across 4 n
    if (tid < DD) {
        const float* lvd = log_vec + b * HH * DD + tid;
        float o0 = 0.f, o1 = 0.f, o2 = 0.f, o3 = 0.f;
#pragma unroll 4
        for (int h = 0; h < HH; h++) {
            float v = lvd[h * DD];
            o0 = fmaf(at_s[0][h], v, o0);
            o1 = fmaf(at_s[1][h], v, o1);
            o2 = fmaf(at_s[2][h], v, o2);
            o3 = fmaf(at_s[3][h], v, o3);
        }
        int nbase = b * NN + ng * 4;
        out[(nbase + 0) * DD + tid] = o0;
        out[(nbase + 1) * DD + tid] = o1;
        out[(nbase + 2) * DD + tid] = o2;
        out[(nbase + 3) * DD + tid] = o3;
    }
}

// ---------------- launch ----------------
extern "C" void kernel_launch(void* const* d_in, const int* in_sizes, int n_in,
                              void* d_out, int out_size) {
    const float* log_vec  = (const float*)d_in[0];   // [64,100,400] f32
    const int*   log_mask = (const int*)d_in[1];     // [64,100] i32
    const float* news_vec = (const float*)d_in[2];   // [64,32,400] f32
    const float* W1       = (const float*)d_in[3];   // [200,800] f32
    const float* b1       = (const float*)d_in[4];   // [200] f32
    const float* W2       = (const float*)d_in[5];   // [1,200] f32
    const float* b2       = (const float*)d_in[6];   // [1] f32
    float* out = (float*)d_out;                      // [64,32,400] f32

    // fused pl+pn GEMM: 100 pl row-blocks + 32 pn row-blocks, 4 col-blocks
    gemm_kernel<<<dim3(4, 132), 128>>>(log_vec, news_vec, W1, b1);

    // fused tanh + softmax + attention: 512 blocks x 512 threads = 8192 warps
    attn_kernel<<<dim3(NN / 4, BB), 512>>>(log_vec, log_mask, W2, b2, out);
}

// round 7
// speedup vs baseline: 1.2140x; 1.0128x over previous
#include <cuda_runtime.h>

// Problem constants: B=64, N=32, H=100, D=400, A=200
#define BB 64
#define NN 32
#define HH 100
#define DD 400
#define AA 200

// Scratch (allocation-free: __device__ globals)
__device__ float g_pl[BB * HH * AA];   // [b][h][a] : log_vec @ Wl^T + b1
__device__ float g_pn[BB * NN * AA];   // [b][n][a] : news_vec @ Wn^T

typedef unsigned long long ull;

// ---------------- helpers ----------------
__device__ __forceinline__ ull fma2(ull a, ull b, ull c) {
    ull d;
    asm("fma.rn.f32x2 %0, %1, %2, %3;" : "=l"(d) : "l"(a), "l"(b), "l"(c));
    return d;
}
__device__ __forceinline__ float tanh_fast(float x) {
    float y;
    asm("tanh.approx.f32 %0, %1;" : "=f"(y) : "f"(x));
    return y;
}

// ---------------- Phase 1: fused GEMM (pl + pn in one launch) ----------------
// by < 100 : pl rows (log_vec, Wl = W1[:,400:800], +b1)
// by >= 100: pn rows (news_vec, Wn = W1[:,0:400])
// BM=64, BN=64, BK=16, 128 threads, 8m x 4a per-thread tile, f32x2 FMA.
__global__ __launch_bounds__(128) void gemm_kernel(
    const float* __restrict__ log_vec, const float* __restrict__ news_vec,
    const float* __restrict__ W1, const float* __restrict__ b1)
{
    const int BK = 16;
    __shared__ float Xs2[BK][132];   // [k][2*r] duplicated pairs
    __shared__ float Ws[BK][68];     // [k][a]

    int by = blockIdx.y;
    const float* X;
    float* out;
    int koff, bm;
    bool add_bias;
    if (by < 100) { X = log_vec;  out = g_pl; koff = DD; bm = by * 64;         add_bias = true;  }
    else          { X = news_vec; out = g_pn; koff = 0;  bm = (by - 100) * 64; add_bias = false; }
    int bn = blockIdx.x * 64;

    int tid = threadIdx.x;
    int tx = tid & 15;      // a-group (4 cols)
    int ty = tid >> 4;      // m-group (8 rows)

    float4 xr[2], wr[2];

    auto ldg_tiles = [&](int k0) {
#pragma unroll
        for (int u = 0; u < 2; u++) {
            int idx = tid + u * 128;
            int r = idx >> 2;
            int kk = (idx & 3) << 2;
            xr[u] = *reinterpret_cast<const float4*>(X + (bm + r) * DD + k0 + kk);
            int arow = bn + r;
            wr[u] = (arow < AA)
                ? *reinterpret_cast<const float4*>(W1 + arow * (2 * DD) + koff + k0 + kk)
                : make_float4(0.f, 0.f, 0.f, 0.f);
        }
    };
    auto sts_tiles = [&]() {
#pragma unroll
        for (int u = 0; u < 2; u++) {
            int idx = tid + u * 128;
            int r = idx >> 2;
            int kk = (idx & 3) << 2;
            float xv[4] = {xr[u].x, xr[u].y, xr[u].z, xr[u].w};
            float wv[4] = {wr[u].x, wr[u].y, wr[u].z, wr[u].w};
#pragma unroll
            for (int j = 0; j < 4; j++) {
                *reinterpret_cast<float2*>(&Xs2[kk + j][2 * r]) = make_float2(xv[j], xv[j]);
                Ws[kk + j][r] = wv[j];
            }
        }
    };

    ull acc[8][2];
#pragma unroll
    for (int i = 0; i < 8; i++) { acc[i][0] = 0ULL; acc[i][1] = 0ULL; }

    ldg_tiles(0);
    for (int kb = 0; kb < DD / BK; kb++) {
        __syncthreads();
        sts_tiles();
        __syncthreads();
        if (kb + 1 < DD / BK) ldg_tiles((kb + 1) * BK);

#pragma unroll
        for (int k = 0; k < BK; k++) {
            float4 xd0 = *reinterpret_cast<float4*>(&Xs2[k][ty * 16 + 0]);
            float4 xd1 = *reinterpret_cast<float4*>(&Xs2[k][ty * 16 + 4]);
            float4 xd2 = *reinterpret_cast<float4*>(&Xs2[k][ty * 16 + 8]);
            float4 xd3 = *reinterpret_cast<float4*>(&Xs2[k][ty * 16 + 12]);
            ulonglong2 wq = *reinterpret_cast<ulonglong2*>(&Ws[k][tx * 4]);
            ull xp[8];
            xp[0] = reinterpret_cast<ull*>(&xd0)[0];
            xp[1] = reinterpret_cast<ull*>(&xd0)[1];
            xp[2] = reinterpret_cast<ull*>(&xd1)[0];
            xp[3] = reinterpret_cast<ull*>(&xd1)[1];
            xp[4] = reinterpret_cast<ull*>(&xd2)[0];
            xp[5] = reinterpret_cast<ull*>(&xd2)[1];
            xp[6] = reinterpret_cast<ull*>(&xd3)[0];
            xp[7] = reinterpret_cast<ull*>(&xd3)[1];
#pragma unroll
            for (int i = 0; i < 8; i++) {
                acc[i][0] = fma2(xp[i], wq.x, acc[i][0]);
                acc[i][1] = fma2(xp[i], wq.y, acc[i][1]);
            }
        }
    }

#pragma unroll
    for (int i = 0; i < 8; i++) {
        int m = bm + ty * 8 + i;
#pragma unroll
        for (int jc = 0; jc < 2; jc++) {
            int a0 = bn + tx * 4 + jc * 2;
            if (a0 < AA) {
                float2 v = *reinterpret_cast<float2*>(&acc[i][jc]);
                if (add_bias) { v.x += b1[a0]; v.y += b1[a0 + 1]; }
                *reinterpret_cast<float2*>(out + m * AA + a0) = v;
            }
        }
    }
}

// ---------------- Phase 2: fused tanh-attention (float4 / low-instr) ----------------
// Block = (b, group of 4 n), 512 threads, grid 512.
// Thread t -> (nsub = t>>7, h = t&127), one (n,h) logit chain, float4 a-steps:
// per 4 tanh: 3x LDS.128 + 4x(FADD,MUFU,FMA) = 15 instrs (was 24).
#define CS 40          // a-chunk width (200 = 5 * 40)
#define CPAD 44        // words/row: 16B-aligned rows; LDS.128 phase banks 12h%32 distinct
 
__global__ __launch_bounds__(512, 3) void attn_kernel(
    const float* __restrict__ log_vec, const int* __restrict__ log_mask,
    const float* __restrict__ W2, const float* __restrict__ b2,
    float* __restrict__ out)
{
    __shared__ __align__(16) float pl_s[HH][CPAD];   // 17.6 KB
    __shared__ __align__(16) float pn_s[4][AA];      // 3.2 KB
    __shared__ __align__(16) float w2_s[AA];         // 0.8 KB
    __shared__ __align__(16) float4 at4_s[HH];       // 1.6 KB, transposed attn

    int b = blockIdx.y;
    int ng = blockIdx.x;               // 0..7
    int tid = threadIdx.x;
    int lane = tid & 31, warp = tid >> 5;

    // stage pn (4 rows = 200 float4) and W2 (50 float4) in one pass
    const float4* png = reinterpret_cast<const float4*>(g_pn + (b * NN + ng * 4) * AA);
    if (tid < 4 * AA / 4)
        reinterpret_cast<float4*>(&pn_s[0][0])[tid] = png[tid];
    else if (tid < 4 * AA / 4 + AA / 4)
        reinterpret_cast<float4*>(w2_s)[tid - 4 * AA / 4] =
            reinterpret_cast<const float4*>(W2)[tid - 4 * AA / 4];

    const int nsub = tid >> 7;         // 0..3
    const int hh = tid & 127;          // thread's h (valid if < 100)
    const float* pnr = pn_s[nsub];
    float acc0 = 0.f, acc1 = 0.f;
    const float* plg = g_pl + b * HH * AA;
    float b2v = b2[0];

    for (int a0 = 0; a0 < AA; a0 += CS) {
        __syncthreads();               // protect pl_s from previous chunk's readers
        // cooperative coalesced load of pl[:, a0:a0+40]  (100 rows x 10 float4)
        for (int i = tid; i < HH * (CS / 4); i += 512) {
            int row = i / (CS / 4);
            int c = (i % (CS / 4)) * 4;
            float4 v = *reinterpret_cast<const float4*>(plg + row * AA + a0 + c);
            *reinterpret_cast<float4*>(&pl_s[row][c]) = v;
        }
        __syncthreads();

        if (hh < HH) {
            const float4* plr = reinterpret_cast<const float4*>(&pl_s[hh][0]);
            const float4* pn4 = reinterpret_cast<const float4*>(pnr + a0);
            const float4* w24 = reinterpret_cast<const float4*>(w2_s + a0);
#pragma unroll
            for (int q = 0; q < CS / 4; q++) {
                float4 p = plr[q];     // conflict-free LDS.128
                float4 nv = pn4[q];    // broadcast LDS.128
                float4 w = w24[q];     // broadcast LDS.128
                acc0 = fmaf(tanh_fast(p.x + nv.x), w.x, acc0);
                acc1 = fmaf(tanh_fast(p.y + nv.y), w.y, acc1);
                acc0 = fmaf(tanh_fast(p.z + nv.z), w.z, acc0);
                acc1 = fmaf(tanh_fast(p.w + nv.w), w.w, acc1);
            }
        }
    }

    if (hh < HH) {
        bool masked = (log_mask[b * HH + hh] == 0);
        float v = masked ? -1e9f : (acc0 + acc1 + b2v);
        reinterpret_cast<float*>(&at4_s[hh])[nsub] = v;   // transposed store
    }
    __syncthreads();

    // softmax over h: warp j (0..3) handles n-index j (strided reads, tiny)
    if (warp < 4) {
        float* atf = reinterpret_cast<float*>(at4_s);
        float m = -3e38f;
        for (int h = lane; h < HH; h += 32) m = fmaxf(m, atf[h * 4 + warp]);
#pragma unroll
        for (int o = 16; o; o >>= 1) m = fmaxf(m, __shfl_xor_sync(0xffffffffu, m, o));
        float s = 0.f;
        for (int h = lane; h < HH; h += 32) {
            float e = __expf(atf[h * 4 + warp] - m);
            atf[h * 4 + warp] = e;
            s += e;
        }
#pragma unroll
        for (int o = 16; o; o >>= 1) s += __shfl_xor_sync(0xffffffffu, s, o);
        float r = 1.f / s;
        for (int h = lane; h < HH; h += 32) atf[h * 4 + warp] *= r;
    }
    __syncthreads();

    // output: thread per d (400 of 512 active); per h: 1 LDG + 1 LDS.128 + 4 FMA
    if (tid < DD) {
        const float* lvd = log_vec + b * HH * DD + tid;
        float o0 = 0.f, o1 = 0.f, o2 = 0.f, o3 = 0.f;
#pragma unroll 4
        for (int h = 0; h < HH; h++) {
            float v = lvd[h * DD];
            float4 w = at4_s[h];       // broadcast LDS.128
            o0 = fmaf(w.x, v, o0);
            o1 = fmaf(w.y, v, o1);
            o2 = fmaf(w.z, v, o2);
            o3 = fmaf(w.w, v, o3);
        }
        int nbase = b * NN + ng * 4;
        out[(nbase + 0) * DD + tid] = o0;
        out[(nbase + 1) * DD + tid] = o1;
        out[(nbase + 2) * DD + tid] = o2;
        out[(nbase + 3) * DD + tid] = o3;
    }
}

// ---------------- launch ----------------
extern "C" void kernel_launch(void* const* d_in, const int* in_sizes, int n_in,
                              void* d_out, int out_size) {
    const float* log_vec  = (const float*)d_in[0];   // [64,100,400] f32
    const int*   log_mask = (const int*)d_in[1];     // [64,100] i32
    const float* news_vec = (const float*)d_in[2];   // [64,32,400] f32
    const float* W1       = (const float*)d_in[3];   // [200,800] f32
    const float* b1       = (const float*)d_in[4];   // [200] f32
    const float* W2       = (const float*)d_in[5];   // [1,200] f32
    const float* b2       = (const float*)d_in[6];   // [1] f32
    float* out = (float*)d_out;                      // [64,32,400] f32

    // fused pl+pn GEMM: 100 pl row-blocks + 32 pn row-blocks, 4 col-blocks
    gemm_kernel<<<dim3(4, 132), 128>>>(log_vec, news_vec, W1, b1);

    // fused tanh + softmax + attention: 512 blocks x 512 threads
    attn_kernel<<<dim3(NN / 4, BB), 512>>>(log_vec, log_mask, W2, b2, out);
}

// round 8
// speedup vs baseline: 1.3096x; 1.0788x over previous
#include <cuda_runtime.h>

// Problem constants: B=64, N=32, H=100, D=400, A=200
#define BB 64
#define NN 32
#define HH 100
#define DD 400
#define AA 200

// Scratch (allocation-free: __device__ globals)
__device__ float g_pl[BB * HH * AA];        // [b][h][a]
__device__ float g_pn[BB * NN * AA];        // [b][n][a]
__device__ float g_logits[BB * HH * NN];    // [b][h][n] masked raw logits

typedef unsigned long long ull;

// ---------------- helpers ----------------
__device__ __forceinline__ ull fma2(ull a, ull b, ull c) {
    ull d;
    asm("fma.rn.f32x2 %0, %1, %2, %3;" : "=l"(d) : "l"(a), "l"(b), "l"(c));
    return d;
}
__device__ __forceinline__ float tanh_fast(float x) {
    float y;
    asm("tanh.approx.f32 %0, %1;" : "=f"(y) : "f"(x));
    return y;
}

// ---------------- Phase 1: fused GEMM (pl + pn in one launch) ----------------
__global__ __launch_bounds__(128) void gemm_kernel(
    const float* __restrict__ log_vec, const float* __restrict__ news_vec,
    const float* __restrict__ W1, const float* __restrict__ b1)
{
    const int BK = 16;
    __shared__ float Xs2[BK][132];   // [k][2*r] duplicated pairs
    __shared__ float Ws[BK][68];     // [k][a]

    int by = blockIdx.y;
    const float* X;
    float* out;
    int koff, bm;
    bool add_bias;
    if (by < 100) { X = log_vec;  out = g_pl; koff = DD; bm = by * 64;         add_bias = true;  }
    else          { X = news_vec; out = g_pn; koff = 0;  bm = (by - 100) * 64; add_bias = false; }
    int bn = blockIdx.x * 64;

    int tid = threadIdx.x;
    int tx = tid & 15;
    int ty = tid >> 4;

    float4 xr[2], wr[2];

    auto ldg_tiles = [&](int k0) {
#pragma unroll
        for (int u = 0; u < 2; u++) {
            int idx = tid + u * 128;
            int r = idx >> 2;
            int kk = (idx & 3) << 2;
            xr[u] = *reinterpret_cast<const float4*>(X + (bm + r) * DD + k0 + kk);
            int arow = bn + r;
            wr[u] = (arow < AA)
                ? *reinterpret_cast<const float4*>(W1 + arow * (2 * DD) + koff + k0 + kk)
                : make_float4(0.f, 0.f, 0.f, 0.f);
        }
    };
    auto sts_tiles = [&]() {
#pragma unroll
        for (int u = 0; u < 2; u++) {
            int idx = tid + u * 128;
            int r = idx >> 2;
            int kk = (idx & 3) << 2;
            float xv[4] = {xr[u].x, xr[u].y, xr[u].z, xr[u].w};
            float wv[4] = {wr[u].x, wr[u].y, wr[u].z, wr[u].w};
#pragma unroll
            for (int j = 0; j < 4; j++) {
                *reinterpret_cast<float2*>(&Xs2[kk + j][2 * r]) = make_float2(xv[j], xv[j]);
                Ws[kk + j][r] = wv[j];
            }
        }
    };

    ull acc[8][2];
#pragma unroll
    for (int i = 0; i < 8; i++) { acc[i][0] = 0ULL; acc[i][1] = 0ULL; }

    ldg_tiles(0);
    for (int kb = 0; kb < DD / BK; kb++) {
        __syncthreads();
        sts_tiles();
        __syncthreads();
        if (kb + 1 < DD / BK) ldg_tiles((kb + 1) * BK);

#pragma unroll
        for (int k = 0; k < BK; k++) {
            float4 xd0 = *reinterpret_cast<float4*>(&Xs2[k][ty * 16 + 0]);
            float4 xd1 = *reinterpret_cast<float4*>(&Xs2[k][ty * 16 + 4]);
            float4 xd2 = *reinterpret_cast<float4*>(&Xs2[k][ty * 16 + 8]);
            float4 xd3 = *reinterpret_cast<float4*>(&Xs2[k][ty * 16 + 12]);
            ulonglong2 wq = *reinterpret_cast<ulonglong2*>(&Ws[k][tx * 4]);
            ull xp[8];
            xp[0] = reinterpret_cast<ull*>(&xd0)[0];
            xp[1] = reinterpret_cast<ull*>(&xd0)[1];
            xp[2] = reinterpret_cast<ull*>(&xd1)[0];
            xp[3] = reinterpret_cast<ull*>(&xd1)[1];
            xp[4] = reinterpret_cast<ull*>(&xd2)[0];
            xp[5] = reinterpret_cast<ull*>(&xd2)[1];
            xp[6] = reinterpret_cast<ull*>(&xd3)[0];
            xp[7] = reinterpret_cast<ull*>(&xd3)[1];
#pragma unroll
            for (int i = 0; i < 8; i++) {
                acc[i][0] = fma2(xp[i], wq.x, acc[i][0]);
                acc[i][1] = fma2(xp[i], wq.y, acc[i][1]);
            }
        }
    }

#pragma unroll
    for (int i = 0; i < 8; i++) {
        int m = bm + ty * 8 + i;
#pragma unroll
        for (int jc = 0; jc < 2; jc++) {
            int a0 = bn + tx * 4 + jc * 2;
            if (a0 < AA) {
                float2 v = *reinterpret_cast<float2*>(&acc[i][jc]);
                if (add_bias) { v.x += b1[a0]; v.y += b1[a0 + 1]; }
                *reinterpret_cast<float2*>(out + m * AA + a0) = v;
            }
        }
    }
}

// ---------------- Phase 2a: logits (barrier-free mainloop) ----------------
// Block = (h-tile of 20, b), 640 threads = 20 warps. Warp = one h, lane = n.
// pl[h][a], w2[a] -> LDS broadcast; pn[n][a] -> conflict-free LDS.128 (stride 212).
#define HT 20
#define PNP 212    // 212%32=20 -> phase banks 20n%32 distinct; 212%4==0 -> 16B aligned

__global__ __launch_bounds__(640, 2) void logits_kernel(
    const int* __restrict__ log_mask, const float* __restrict__ W2,
    const float* __restrict__ b2)
{
    __shared__ __align__(16) float pl_s[HT][AA];    // 16 KB
    __shared__ __align__(16) float pn_s[NN][PNP];   // 27.1 KB
    __shared__ __align__(16) float w2_s[AA];        // 0.8 KB

    int ht = blockIdx.x;           // 0..4
    int b = blockIdx.y;
    int tid = threadIdx.x;
    int lane = tid & 31;           // n
    int wid = tid >> 5;            // h within tile (0..19)
    int h = ht * HT + wid;

    // stage pl rows for this h-tile (20 x 200), coalesced
    const float4* plg = reinterpret_cast<const float4*>(g_pl + (b * HH + ht * HT) * AA);
    for (int i = tid; i < HT * AA / 4; i += 640) {
        int r = i / (AA / 4), c4 = i % (AA / 4);
        *reinterpret_cast<float4*>(&pl_s[r][c4 * 4]) = plg[i];
    }
    // stage pn[b] (32 x 200) into padded rows
    const float4* png = reinterpret_cast<const float4*>(g_pn + b * NN * AA);
    for (int i = tid; i < NN * AA / 4; i += 640) {
        int r = i / (AA / 4), c4 = i % (AA / 4);
        *reinterpret_cast<float4*>(&pn_s[r][c4 * 4]) = png[i];
    }
    // stage W2
    for (int i = tid; i < AA / 4; i += 640)
        reinterpret_cast<float4*>(w2_s)[i] = reinterpret_cast<const float4*>(W2)[i];
    __syncthreads();               // the ONLY barrier

    const float4* pn4 = reinterpret_cast<const float4*>(&pn_s[lane][0]);
    const float4* pl4 = reinterpret_cast<const float4*>(&pl_s[wid][0]);
    const float4* w24 = reinterpret_cast<const float4*>(w2_s);

    float acc0 = 0.f, acc1 = 0.f;
#pragma unroll 5
    for (int q = 0; q < AA / 4; q++) {
        float4 p = pl4[q];         // broadcast (1 wavefront)
        float4 nv = pn4[q];        // conflict-free LDS.128
        float4 w = w24[q];         // broadcast
        acc0 = fmaf(tanh_fast(p.x + nv.x), w.x, acc0);
        acc1 = fmaf(tanh_fast(p.y + nv.y), w.y, acc1);
        acc0 = fmaf(tanh_fast(p.z + nv.z), w.z, acc0);
        acc1 = fmaf(tanh_fast(p.w + nv.w), w.w, acc1);
    }

    bool masked = (log_mask[b * HH + h] == 0);   // warp-uniform
    float v = masked ? -1e9f : (acc0 + acc1 + b2[0]);
    g_logits[(b * HH + h) * NN + lane] = v;      // coalesced 128B per warp
}

// ---------------- Phase 2b: softmax + attention output ----------------
// Block = (n-group of 8, b), 512 threads. Stage logits [100][8], softmax per n
// (warp j <- n j), then out[n][d] = sum_h attn * log_vec (thread = d).
__global__ __launch_bounds__(512) void out_kernel(
    const float* __restrict__ log_vec, float* __restrict__ out)
{
    __shared__ __align__(16) float at_s[HH][8];    // 3.2 KB

    int ng = blockIdx.x;           // 0..3
    int b = blockIdx.y;
    int tid = threadIdx.x;
    int lane = tid & 31, warp = tid >> 5;

    // stage logits columns [100][8]
    const float* lg = g_logits + b * HH * NN + ng * 8;
    for (int i = tid; i < HH * 8; i += 512) {
        int h = i >> 3, j = i & 7;
        at_s[h][j] = lg[h * NN + j];
    }
    __syncthreads();

    // softmax: warp j (0..7) owns n-index j
    if (warp < 8) {
        float m = -3e38f;
        for (int h = lane; h < HH; h += 32) m = fmaxf(m, at_s[h][warp]);
#pragma unroll
        for (int o = 16; o; o >>= 1) m = fmaxf(m, __shfl_xor_sync(0xffffffffu, m, o));
        float s = 0.f;
        for (int h = lane; h < HH; h += 32) {
            float e = __expf(at_s[h][warp] - m);
            at_s[h][warp] = e;
            s += e;
        }
#pragma unroll
        for (int o = 16; o; o >>= 1) s += __shfl_xor_sync(0xffffffffu, s, o);
        float r = 1.f / s;
        for (int h = lane; h < HH; h += 32) at_s[h][warp] *= r;
    }
    __syncthreads();

    // output: thread = d (400 of 512 active); attn rows via 2 broadcast LDS.128
    if (tid < DD) {
        const float* lvd = log_vec + b * HH * DD + tid;
        float o0 = 0.f, o1 = 0.f, o2 = 0.f, o3 = 0.f;
        float o4 = 0.f, o5 = 0.f, o6 = 0.f, o7 = 0.f;
#pragma unroll 4
        for (int h = 0; h < HH; h++) {
            float v = lvd[h * DD];
            float4 w0 = *reinterpret_cast<float4*>(&at_s[h][0]);
            float4 w1 = *reinterpret_cast<float4*>(&at_s[h][4]);
            o0 = fmaf(w0.x, v, o0);
            o1 = fmaf(w0.y, v, o1);
            o2 = fmaf(w0.z, v, o2);
            o3 = fmaf(w0.w, v, o3);
            o4 = fmaf(w1.x, v, o4);
            o5 = fmaf(w1.y, v, o5);
            o6 = fmaf(w1.z, v, o6);
            o7 = fmaf(w1.w, v, o7);
        }
        int nbase = b * NN + ng * 8;
        out[(nbase + 0) * DD + tid] = o0;
        out[(nbase + 1) * DD + tid] = o1;
        out[(nbase + 2) * DD + tid] = o2;
        out[(nbase + 3) * DD + tid] = o3;
        out[(nbase + 4) * DD + tid] = o4;
        out[(nbase + 5) * DD + tid] = o5;
        out[(nbase + 6) * DD + tid] = o6;
        out[(nbase + 7) * DD + tid] = o7;
    }
}

// ---------------- launch ----------------
extern "C" void kernel_launch(void* const* d_in, const int* in_sizes, int n_in,
                              void* d_out, int out_size) {
    const float* log_vec  = (const float*)d_in[0];   // [64,100,400] f32
    const int*   log_mask = (const int*)d_in[1];     // [64,100] i32
    const float* news_vec = (const float*)d_in[2];   // [64,32,400] f32
    const float* W1       = (const float*)d_in[3];   // [200,800] f32
    const float* b1       = (const float*)d_in[4];   // [200] f32
    const float* W2       = (const float*)d_in[5];   // [1,200] f32
    const float* b2       = (const float*)d_in[6];   // [1] f32
    float* out = (float*)d_out;                      // [64,32,400] f32

    gemm_kernel<<<dim3(4, 132), 128>>>(log_vec, news_vec, W1, b1);
    logits_kernel<<<dim3(HH / HT, BB), 640>>>(log_mask, W2, b2);
    out_kernel<<<dim3(NN / 8, BB), 512>>>(log_vec, out);
}

// round 10
// speedup vs baseline: 2.1387x; 1.6331x over previous
#include <cuda_runtime.h>
#include <cuda_bf16.h>
#include <cstdint>

// Problem constants: B=64, N=32, H=100, D=400, A=200
#define BB 64
#define NN 32
#define HH 100
#define DD 400
#define AA 200

// Scratch (allocation-free: __device__ globals)
__device__ float g_pl[BB * HH * AA];        // [b][h][a]
__device__ float g_pn[BB * NN * AA];        // [b][n][a]
__device__ float g_logits[BB * HH * NN];    // [b][h][n] masked raw logits

// ---------------- helpers ----------------
__device__ __forceinline__ float tanh_fast(float x) {
    float y;
    asm("tanh.approx.f32 %0, %1;" : "=f"(y) : "f"(x));
    return y;
}
__device__ __forceinline__ uint32_t s2u(const void* p) {
    uint32_t a;
    asm("{ .reg .u64 t; cvta.to.shared.u64 t, %1; cvt.u32.u64 %0, t; }" : "=r"(a) : "l"(p));
    return a;
}
__device__ __forceinline__ uint32_t bpack(__nv_bfloat16 a, __nv_bfloat16 b) {
    __nv_bfloat162 t(a, b);
    return *reinterpret_cast<uint32_t*>(&t);
}
__device__ __forceinline__ void ldmx4(uint32_t* r, uint32_t addr) {
    asm volatile("ldmatrix.sync.aligned.m8n8.x4.shared.b16 {%0,%1,%2,%3}, [%4];"
                 : "=r"(r[0]), "=r"(r[1]), "=r"(r[2]), "=r"(r[3]) : "r"(addr));
}
__device__ __forceinline__ void hmma(float* d, const uint32_t* a,
                                     uint32_t b0, uint32_t b1) {
    asm("mma.sync.aligned.m16n8k16.row.col.f32.bf16.bf16.f32 "
        "{%0,%1,%2,%3}, {%4,%5,%6,%7}, {%8,%9}, {%0,%1,%2,%3};"
        : "+f"(d[0]), "+f"(d[1]), "+f"(d[2]), "+f"(d[3])
        : "r"(a[0]), "r"(a[1]), "r"(a[2]), "r"(a[3]), "r"(b0), "r"(b1));
}

// ---------------- Phase 1: HMMA bf16 3-pass split-GEMM ----------------
// out[m][a] = sum_k X[m][k] * W1[a][koff+k]   (f32 via Ah*Bh + Ah*Bl + Al*Bh)
// CTA 128m x 64a, 256 thr = 8 warps (4m x 2n), warp 32x32, K-chunks of 32.
#define GM 128
#define GN 64
#define KC 32
#define NCH 13            // 13*32 = 416 >= 400 (zero-padded)
#define ASTR 40           // smem row stride in bf16 (80B: ldmatrix conflict-free)

__global__ __launch_bounds__(256) void gemm_tc_kernel(
    const float* __restrict__ log_vec, const float* __restrict__ news_vec,
    const float* __restrict__ W1, const float* __restrict__ b1)
{
    __shared__ __align__(16) __nv_bfloat16 Ah[GM * ASTR], Al[GM * ASTR];
    __shared__ __align__(16) __nv_bfloat16 Bh[GN * ASTR], Bl[GN * ASTR];
    __shared__ float b1s[GN];

    int tid = threadIdx.x, lane = tid & 31, wid = tid >> 5;
    int wm = wid & 3;          // m-group (32 rows)
    int wn = wid >> 2;         // n-group (32 cols)

    int by = blockIdx.y;
    const float* X;
    float* outp;
    int koff, bm;
    bool bias;
    if (by < 50) { X = log_vec;  outp = g_pl; koff = DD; bm = by * GM;        bias = true;  }
    else         { X = news_vec; outp = g_pn; koff = 0;  bm = (by - 50) * GM; bias = false; }
    int bn = blockIdx.x * GN;

    if (tid < GN) b1s[tid] = (bias && bn + tid < AA) ? b1[bn + tid] : 0.f;

    uint32_t sAh = s2u(Ah), sAl = s2u(Al), sBh = s2u(Bh), sBl = s2u(Bl);

    // ldg staging regs
    float4 xa[4], xb[2];
    auto ldgA = [&](int c) {
        int k0 = c * KC;
#pragma unroll
        for (int u = 0; u < 4; u++) {
            int idx = tid + u * 256;           // 0..1023
            int r = idx >> 3, c4 = (idx & 7) << 2;
            int k = k0 + c4;
            xa[u] = (k < DD)
                ? *reinterpret_cast<const float4*>(X + (size_t)(bm + r) * DD + k)
                : make_float4(0.f, 0.f, 0.f, 0.f);
        }
    };
    auto ldgB = [&](int c) {
        int k0 = c * KC;
#pragma unroll
        for (int u = 0; u < 2; u++) {
            int idx = tid + u * 256;           // 0..511
            int r = idx >> 3, c4 = (idx & 7) << 2;
            int k = k0 + c4, a = bn + r;
            xb[u] = (a < AA && k < DD)
                ? *reinterpret_cast<const float4*>(W1 + (size_t)a * (2 * DD) + koff + k)
                : make_float4(0.f, 0.f, 0.f, 0.f);
        }
    };
    auto cvt_sts = [&](__nv_bfloat16* hi, __nv_bfloat16* lo, int r, int c4, float4 v) {
        __nv_bfloat16 h0 = __float2bfloat16(v.x), h1 = __float2bfloat16(v.y);
        __nv_bfloat16 h2 = __float2bfloat16(v.z), h3 = __float2bfloat16(v.w);
        __nv_bfloat16 l0 = __float2bfloat16(v.x - __bfloat162float(h0));
        __nv_bfloat16 l1 = __float2bfloat16(v.y - __bfloat162float(h1));
        __nv_bfloat16 l2 = __float2bfloat16(v.z - __bfloat162float(h2));
        __nv_bfloat16 l3 = __float2bfloat16(v.w - __bfloat162float(h3));
        *reinterpret_cast<uint2*>(hi + r * ASTR + c4) = make_uint2(bpack(h0, h1), bpack(h2, h3));
        *reinterpret_cast<uint2*>(lo + r * ASTR + c4) = make_uint2(bpack(l0, l1), bpack(l2, l3));
    };

    float acc[8][4];           // [mt*4 + ntile][4]
#pragma unroll
    for (int i = 0; i < 8; i++)
#pragma unroll
        for (int j = 0; j < 4; j++) acc[i][j] = 0.f;

    ldgA(0); ldgB(0);
    for (int c = 0; c < NCH; c++) {
        __syncthreads();
#pragma unroll
        for (int u = 0; u < 4; u++) {
            int idx = tid + u * 256;
            cvt_sts(Ah, Al, idx >> 3, (idx & 7) << 2, xa[u]);
        }
#pragma unroll
        for (int u = 0; u < 2; u++) {
            int idx = tid + u * 256;
            cvt_sts(Bh, Bl, idx >> 3, (idx & 7) << 2, xb[u]);
        }
        __syncthreads();
        if (c + 1 < NCH) { ldgA(c + 1); ldgB(c + 1); }

#pragma unroll
        for (int ks = 0; ks < 2; ks++) {
            int kcol = ks * 16 + ((lane >> 4) << 3);
            // fragment smem offsets (lane-dependent), bytes
            uint32_t aoff = (uint32_t)(((wm * 32 + (lane & 15)) * ASTR + kcol) * 2);
            uint32_t boff = (uint32_t)(((wn * 32 + (lane & 15)) * ASTR + kcol) * 2);
            const uint32_t mstep = 16 * ASTR * 2;

            uint32_t ah[8], al[8], bh[8], bl[8];
            ldmx4(ah, sAh + aoff); ldmx4(ah + 4, sAh + aoff + mstep);
            ldmx4(al, sAl + aoff); ldmx4(al + 4, sAl + aoff + mstep);
            ldmx4(bh, sBh + boff); ldmx4(bh + 4, sBh + boff + mstep);
            ldmx4(bl, sBl + boff); ldmx4(bl + 4, sBl + boff + mstep);

#pragma unroll
            for (int mt = 0; mt < 2; mt++)
#pragma unroll
                for (int j = 0; j < 4; j++) {
                    int ng = j >> 1, sub = j & 1;
                    float* d = acc[mt * 4 + j];
                    hmma(d, ah + mt * 4, bh[ng * 4 + sub], bh[ng * 4 + sub + 2]); // hi*hi
                    hmma(d, ah + mt * 4, bl[ng * 4 + sub], bl[ng * 4 + sub + 2]); // hi*lo
                    hmma(d, al + mt * 4, bh[ng * 4 + sub], bh[ng * 4 + sub + 2]); // lo*hi
                }
        }
    }

    // epilogue: direct float2 stores (+bias; b1s zeroed for pn)
#pragma unroll
    for (int mt = 0; mt < 2; mt++)
#pragma unroll
        for (int j = 0; j < 4; j++) {
            int m0 = bm + wm * 32 + mt * 16 + (lane >> 2);
            int ln = wn * 32 + j * 8 + 2 * (lane & 3);
            int a0 = bn + ln;
            if (a0 < AA) {
                const float* d = acc[mt * 4 + j];
                float bx = b1s[ln], by2 = b1s[ln + 1];
                *reinterpret_cast<float2*>(outp + (size_t)m0 * AA + a0) =
                    make_float2(d[0] + bx, d[1] + by2);
                *reinterpret_cast<float2*>(outp + (size_t)(m0 + 8) * AA + a0) =
                    make_float2(d[2] + bx, d[3] + by2);
            }
        }
}

// ---------------- Phase 2a: logits (barrier-free mainloop) ----------------
#define HT 20
#define PNP 212

__global__ __launch_bounds__(640, 2) void logits_kernel(
    const int* __restrict__ log_mask, const float* __restrict__ W2,
    const float* __restrict__ b2)
{
    __shared__ __align__(16) float pl_s[HT][AA];
    __shared__ __align__(16) float pn_s[NN][PNP];
    __shared__ __align__(16) float w2_s[AA];

    int ht = blockIdx.x;
    int b = blockIdx.y;
    int tid = threadIdx.x;
    int lane = tid & 31;           // n
    int wid = tid >> 5;            // h within tile
    int h = ht * HT + wid;

    const float4* plg = reinterpret_cast<const float4*>(g_pl + (b * HH + ht * HT) * AA);
    for (int i = tid; i < HT * AA / 4; i += 640) {
        int r = i / (AA / 4), c4 = i % (AA / 4);
        *reinterpret_cast<float4*>(&pl_s[r][c4 * 4]) = plg[i];
    }
    const float4* png = reinterpret_cast<const float4*>(g_pn + b * NN * AA);
    for (int i = tid; i < NN * AA / 4; i += 640) {
        int r = i / (AA / 4), c4 = i % (AA / 4);
        *reinterpret_cast<float4*>(&pn_s[r][c4 * 4]) = png[i];
    }
    for (int i = tid; i < AA / 4; i += 640)
        reinterpret_cast<float4*>(w2_s)[i] = reinterpret_cast<const float4*>(W2)[i];
    __syncthreads();

    const float4* pn4 = reinterpret_cast<const float4*>(&pn_s[lane][0]);
    const float4* pl4 = reinterpret_cast<const float4*>(&pl_s[wid][0]);
    const float4* w24 = reinterpret_cast<const float4*>(w2_s);

    float acc0 = 0.f, acc1 = 0.f;
#pragma unroll 5
    for (int q = 0; q < AA / 4; q++) {
        float4 p = pl4[q];
        float4 nv = pn4[q];
        float4 w = w24[q];
        acc0 = fmaf(tanh_fast(p.x + nv.x), w.x, acc0);
        acc1 = fmaf(tanh_fast(p.y + nv.y), w.y, acc1);
        acc0 = fmaf(tanh_fast(p.z + nv.z), w.z, acc0);
        acc1 = fmaf(tanh_fast(p.w + nv.w), w.w, acc1);
    }

    bool masked = (log_mask[b * HH + h] == 0);
    float v = masked ? -1e9f : (acc0 + acc1 + b2[0]);
    g_logits[(b * HH + h) * NN + lane] = v;
}

// ---------------- Phase 2b: softmax + attention output ----------------
__global__ __launch_bounds__(512) void out_kernel(
    const float* __restrict__ log_vec, float* __restrict__ out)
{
    __shared__ __align__(16) float at_s[HH][8];

    int ng = blockIdx.x;
    int b = blockIdx.y;
    int tid = threadIdx.x;
    int lane = tid & 31, warp = tid >> 5;

    const float* lg = g_logits + b * HH * NN + ng * 8;
    for (int i = tid; i < HH * 8; i += 512) {
        int h = i >> 3, j = i & 7;
        at_s[h][j] = lg[h * NN + j];
    }
    __syncthreads();

    if (warp < 8) {
        float m = -3e38f;
        for (int h = lane; h < HH; h += 32) m = fmaxf(m, at_s[h][warp]);
#pragma unroll
        for (int o = 16; o; o >>= 1) m = fmaxf(m, __shfl_xor_sync(0xffffffffu, m, o));
        float s = 0.f;
        for (int h = lane; h < HH; h += 32) {
            float e = __expf(at_s[h][warp] - m);
            at_s[h][warp] = e;
            s += e;
        }
#pragma unroll
        for (int o = 16; o; o >>= 1) s += __shfl_xor_sync(0xffffffffu, s, o);
        float r = 1.f / s;
        for (int h = lane; h < HH; h += 32) at_s[h][warp] *= r;
    }
    __syncthreads();

    if (tid < DD) {
        const float* lvd = log_vec + b * HH * DD + tid;
        float o0 = 0.f, o1 = 0.f, o2 = 0.f, o3 = 0.f;
        float o4 = 0.f, o5 = 0.f, o6 = 0.f, o7 = 0.f;
#pragma unroll 4
        for (int h = 0; h < HH; h++) {
            float v = lvd[h * DD];
            float4 w0 = *reinterpret_cast<float4*>(&at_s[h][0]);
            float4 w1 = *reinterpret_cast<float4*>(&at_s[h][4]);
            o0 = fmaf(w0.x, v, o0);
            o1 = fmaf(w0.y, v, o1);
            o2 = fmaf(w0.z, v, o2);
            o3 = fmaf(w0.w, v, o3);
            o4 = fmaf(w1.x, v, o4);
            o5 = fmaf(w1.y, v, o5);
            o6 = fmaf(w1.z, v, o6);
            o7 = fmaf(w1.w, v, o7);
        }
        int nbase = b * NN + ng * 8;
        out[(nbase + 0) * DD + tid] = o0;
        out[(nbase + 1) * DD + tid] = o1;
        out[(nbase + 2) * DD + tid] = o2;
        out[(nbase + 3) * DD + tid] = o3;
        out[(nbase + 4) * DD + tid] = o4;
        out[(nbase + 5) * DD + tid] = o5;
        out[(nbase + 6) * DD + tid] = o6;
        out[(nbase + 7) * DD + tid] = o7;
    }
}

// ---------------- launch ----------------
extern "C" void kernel_launch(void* const* d_in, const int* in_sizes, int n_in,
                              void* d_out, int out_size) {
    const float* log_vec  = (const float*)d_in[0];   // [64,100,400] f32
    const int*   log_mask = (const int*)d_in[1];     // [64,100] i32
    const float* news_vec = (const float*)d_in[2];   // [64,32,400] f32
    const float* W1       = (const float*)d_in[3];   // [200,800] f32
    const float* b1       = (const float*)d_in[4];   // [200] f32
    const float* W2       = (const float*)d_in[5];   // [1,200] f32
    const float* b2       = (const float*)d_in[6];   // [1] f32
    float* out = (float*)d_out;                      // [64,32,400] f32

    gemm_tc_kernel<<<dim3(4, 66), 256>>>(log_vec, news_vec, W1, b1);
    logits_kernel<<<dim3(HH / HT, BB), 640>>>(log_mask, W2, b2);
    out_kernel<<<dim3(NN / 8, BB), 512>>>(log_vec, out);
}